// round 14
// baseline (speedup 1.0000x reference)
#include <cuda_runtime.h>
#include <cuda_fp16.h>
#include <cstdint>

// ---------------------------------------------------------------------------
// BitLinear: out = x @ absmean_quant(w)^T + bias
//   x: [8192, 4096] f32, w: [16384, 4096] f32, bias: [16384] f32
//   out: [8192, 16384] f32   (1.10 TFLOP GEMM)
//
// sm_103 (plain) -> legacy HMMA path (tcgen05 rejected by ptxas):
//   mma.sync.m16n8k16.f32.f16.f16.f32 + ldmatrix, cp.async.bulk + mbarrier.
// R14 = R13 with the refill off-by-2 FIXED: after consuming pair (j, j+1)
// (stages s0,s1) the sync frees s0,s1 and we refill them with chunks j+4,
// j+5 (same stages). Pair-hoisted waits, barrier-free 2-chunk window.
// ---------------------------------------------------------------------------

#define TOK   8192
#define INF   4096
#define OUTF  16384

// ---------------- device scratch (no cudaMalloc allowed) -------------------
__device__ double g_part[1024];  // absum partials (one slot per block, no init)
__device__ float  g_thr;         // 0.7 * mean|w|
// w packed: [n_tile256][k_chunk64][256x64 fp16 SW128-swizzled = 32KB]
__device__ __align__(1024) unsigned char g_wq[(size_t)OUTF * INF * 2];
// x packed: [m_tile128][k_chunk64][128x64 fp16 SW128-swizzled = 16KB]
__device__ __align__(1024) unsigned char g_xh[(size_t)TOK * INF * 2];

// ---------------- PTX helpers ----------------------------------------------
__device__ __forceinline__ uint32_t smem_u32(const void* p) {
    uint32_t a;
    asm("{ .reg .u64 t; cvta.to.shared.u64 t, %1; cvt.u32.u64 %0, t; }"
        : "=r"(a) : "l"(p));
    return a;
}

#define MBARRIER_INIT(addr, cnt) \
    asm volatile("mbarrier.init.shared.b64 [%0], %1;" :: "r"(addr), "r"(cnt) : "memory")

#define MBARRIER_EXPECT_TX(addr, bytes) \
    asm volatile("mbarrier.arrive.expect_tx.shared.b64 _, [%0], %1;" \
                 :: "r"(addr), "r"(bytes) : "memory")

#define MBARRIER_WAIT_PARITY(mbar_smem_addr, phase_parity) do { \
    uint32_t _mbar = (uint32_t)(mbar_smem_addr); \
    uint32_t _parity = (uint32_t)(phase_parity); \
    uint32_t _done; \
    asm volatile( \
        "{\n\t.reg .pred p;\n\t" \
        "mbarrier.try_wait.parity.acquire.cta.shared::cta.b64 p, [%1], %2;\n\t" \
        "selp.b32 %0, 1, 0, p;\n\t}" \
        : "=r"(_done) : "r"(_mbar), "r"(_parity) : "memory"); \
    if (!_done) { \
        asm volatile( \
            "{\n\t.reg .pred P1;\n\t" \
            "WAIT_LOOP_%=:\n\t" \
            "mbarrier.try_wait.parity.acquire.cta.shared::cta.b64 P1, [%0], %1, 0x989680;\n\t" \
            "@P1 bra.uni WAIT_DONE_%=;\n\t" \
            "bra.uni WAIT_LOOP_%=;\n\t" \
            "WAIT_DONE_%=:\n\t}" \
            :: "r"(_mbar), "r"(_parity) : "memory"); \
    } \
} while(0)

// 1D bulk copy gmem -> smem with mbarrier complete_tx (sm_90 baseline)
__device__ __forceinline__ void bulk_g2s(uint32_t dst, const void* src,
                                         uint32_t bytes, uint32_t mbar) {
    asm volatile(
        "cp.async.bulk.shared::cluster.global.mbarrier::complete_tx::bytes "
        "[%0], [%1], %2, [%3];"
        :: "r"(dst), "l"(src), "r"(bytes), "r"(mbar) : "memory");
}

#define LDSM_X4(r0, r1, r2, r3, addr) \
    asm volatile("ldmatrix.sync.aligned.m8n8.x4.shared.b16 {%0,%1,%2,%3}, [%4];" \
                 : "=r"(r0), "=r"(r1), "=r"(r2), "=r"(r3) : "r"(addr))

#define MMA16816(d, a0, a1, a2, a3, b0, b1) \
    asm volatile("mma.sync.aligned.m16n8k16.row.col.f32.f16.f16.f32 " \
                 "{%0,%1,%2,%3}, {%4,%5,%6,%7}, {%8,%9}, {%0,%1,%2,%3};" \
                 : "+f"((d)[0]), "+f"((d)[1]), "+f"((d)[2]), "+f"((d)[3]) \
                 : "r"(a0), "r"(a1), "r"(a2), "r"(a3), "r"(b0), "r"(b1))

// streaming (evict-first) store: keep L2 for A/B tiles
#define STG64_CS(ptr, vx, vy) \
    asm volatile("st.global.cs.v2.f32 [%0], {%1, %2};" \
                 :: "l"(ptr), "f"(vx), "f"(vy) : "memory")

__device__ __forceinline__ uint32_t sw128(uint32_t off) {
    return off ^ ((off >> 3) & 0x70);
}

// ---------------- prep kernels ----------------------------------------------
// fused: absum partials over w (1024 blocks, one slot each, no init needed)
// + x -> fp16 tiled+swizzled conversion (grid-stride).
__global__ void k_prep(const float4* __restrict__ w,
                       const float* __restrict__ x) {
    // ---- part 1: absum partial over w ----
    double s = 0.0;
    const int n4 = OUTF * INF / 4;
    for (int i = blockIdx.x * blockDim.x + threadIdx.x; i < n4;
         i += gridDim.x * blockDim.x) {
        float4 v = w[i];
        s += (double)fabsf(v.x) + (double)fabsf(v.y) +
             (double)fabsf(v.z) + (double)fabsf(v.w);
    }
    for (int o = 16; o; o >>= 1) s += __shfl_xor_sync(0xffffffffu, s, o);
    __shared__ double ws[8];
    if ((threadIdx.x & 31) == 0) ws[threadIdx.x >> 5] = s;
    __syncthreads();
    if (threadIdx.x == 0) {
        double t = 0.0;
        #pragma unroll
        for (int i = 0; i < 8; i++) t += ws[i];
        g_part[blockIdx.x] = t;
    }

    // ---- part 2: convert x -> fp16, tiled+swizzled (8 elems / item) ----
    const unsigned nitems = TOK * INF / 8;   // 4194304
    for (unsigned idx = blockIdx.x * blockDim.x + threadIdx.x; idx < nitems;
         idx += gridDim.x * blockDim.x) {
        unsigned m  = idx >> 9;
        unsigned k0 = (idx & 511u) << 3;
        const float4* p = (const float4*)(x + (size_t)m * INF + k0);
        float4 v0 = p[0], v1 = p[1];
        float a[8] = {v0.x, v0.y, v0.z, v0.w, v1.x, v1.y, v1.z, v1.w};
        unsigned hs[8];
        #pragma unroll
        for (int i = 0; i < 8; i++)
            hs[i] = (unsigned)__half_as_ushort(__float2half_rn(a[i]));
        uint4 u;
        u.x = hs[0] | (hs[1] << 16);
        u.y = hs[2] | (hs[3] << 16);
        u.z = hs[4] | (hs[5] << 16);
        u.w = hs[6] | (hs[7] << 16);
        uint32_t off = sw128((m & 127u) * 128u + (k0 & 63u) * 2u);
        size_t base = ((size_t)(m >> 7) * 64u + (k0 >> 6)) * 16384u + off;
        *(uint4*)(g_xh + base) = u;
    }
}

// reduce the 1024 partials to the threshold scalar
__global__ void k_thr() {
    double s = 0.0;
    for (int i = threadIdx.x; i < 1024; i += 256) s += g_part[i];
    for (int o = 16; o; o >>= 1) s += __shfl_xor_sync(0xffffffffu, s, o);
    __shared__ double ws[8];
    if ((threadIdx.x & 31) == 0) ws[threadIdx.x >> 5] = s;
    __syncthreads();
    if (threadIdx.x == 0) {
        double t = 0.0;
        #pragma unroll
        for (int i = 0; i < 8; i++) t += ws[i];
        g_thr = (float)(t * (0.7 / ((double)OUTF * (double)INF)));
    }
}

// ternarize w -> fp16, tiled+swizzled (8 elems / thread)
__global__ void k_quant_w(const float* __restrict__ w) {
    const float thr = g_thr;
    unsigned idx = blockIdx.x * 256u + threadIdx.x;   // 0 .. 8388607
    unsigned n  = idx >> 9;          // out-feature row
    unsigned k0 = (idx & 511u) << 3; // k group start
    const float4* p = (const float4*)(w + (size_t)n * INF + k0);
    float4 v0 = p[0], v1 = p[1];
    float a[8] = {v0.x, v0.y, v0.z, v0.w, v1.x, v1.y, v1.z, v1.w};
    unsigned hs[8];
    #pragma unroll
    for (int i = 0; i < 8; i++) {
        float t = a[i];
        hs[i] = (fabsf(t) >= thr) ? (t > 0.0f ? 0x3C00u : 0xBC00u) : 0u;
    }
    uint4 u;
    u.x = hs[0] | (hs[1] << 16);
    u.y = hs[2] | (hs[3] << 16);
    u.z = hs[4] | (hs[5] << 16);
    u.w = hs[6] | (hs[7] << 16);
    uint32_t off = sw128((n & 255u) * 128u + (k0 & 63u) * 2u);
    size_t base = ((size_t)(n >> 8) * 64u + (k0 >> 6)) * 32768u + off;
    *(uint4*)(g_wq + base) = u;
}

// ---------------- GEMM --------------------------------------------------------
// Persistent CTAs, 1/SM, 8 warps (2M x 4N, warp tile 64x64). CTA tile
// 128x256xK64. 4-stage continuous cp.async.bulk ring. Per-chunk TMA
// completion; BOTH waits of a pair hoisted to the pair top -> barrier-free
// 2-chunk compute window. __syncthreads once per pair; refill chunks j+4,
// j+5 (the stages just freed), split across tid0/tid32.
static constexpr int TILES = 4096;                   // 64 m x 64 n
static constexpr int KCHUNKS = INF / 64;             // 64 (even)
static constexpr int STAGES = 4;
static constexpr uint32_t A_BYTES = 128u * 128u;     // 16KB
static constexpr uint32_t B_BYTES = 256u * 128u;     // 32KB
static constexpr uint32_t STAGE_BYTES = A_BYTES + B_BYTES;  // 48KB
static constexpr uint32_t SMEM_BYTES = 1024u + STAGES * STAGE_BYTES;

__device__ __forceinline__ void issue_chunk(long j, int bid, int grid,
                                            uint32_t data, uint32_t mb_full) {
    const int t = bid + (int)(j >> 6) * grid;   // tile for this chunk
    const int c = (int)(j & 63);
    const int m = t & 63;
    const int n = t >> 6;
    const int s = (int)(j & (STAGES - 1));
    const uint32_t st = data + (uint32_t)s * STAGE_BYTES;
    MBARRIER_EXPECT_TX(mb_full + 8 * s, STAGE_BYTES);
    bulk_g2s(st, g_xh + ((size_t)m * 64u + c) * A_BYTES, A_BYTES, mb_full + 8 * s);
    bulk_g2s(st + A_BYTES, g_wq + ((size_t)n * 64u + c) * B_BYTES, B_BYTES,
             mb_full + 8 * s);
}

__global__ void __launch_bounds__(256, 1) k_gemm(float* __restrict__ out,
                                                 const float* __restrict__ bias,
                                                 int grid) {
    extern __shared__ char smem_raw[];
    uint32_t base = (smem_u32(smem_raw) + 1023u) & ~1023u;
    const uint32_t mb_full = base;           // STAGES x 8B mbarriers
    const uint32_t data    = base + 1024u;

    const int tid  = threadIdx.x;
    const int wid  = tid >> 5;
    const int lane = tid & 31;
    const int wm = wid & 1;        // 2 warps along M
    const int wn = wid >> 1;       // 4 warps along N
    const int bid = blockIdx.x;

    if (tid == 0) {
        #pragma unroll
        for (int s = 0; s < STAGES; s++) MBARRIER_INIT(mb_full + 8 * s, 1);
    }
    __syncthreads();

    const int ntile = (bid < TILES) ? ((TILES - 1 - bid) / grid + 1) : 0;
    if (ntile == 0) return;
    const long totchunks = (long)ntile * KCHUNKS;

    // prologue: fill all STAGES slots of the continuous stream
    if (tid == 0) {
        const long pre = totchunks < STAGES ? totchunks : STAGES;
        for (long j = 0; j < pre; j++) issue_chunk(j, bid, grid, data, mb_full);
    }

    // per-thread ldmatrix sub-offsets (un-swizzled), swizzle applied per access
    const uint32_t rowA = (uint32_t)(wm * 64 + (lane & 7) + ((lane >> 3) & 1) * 8);
    const uint32_t kbA  = (uint32_t)((lane >> 4) * 16);
    const uint32_t rowB = (uint32_t)(wn * 64 + ((lane >> 4) & 1) * 8 + (lane & 7));
    const uint32_t kbB  = (uint32_t)(((lane >> 3) & 1) * 16);

    long j = 0;   // pair-aligned chunk counter (points at current pair start)
    for (int ti = 0; ti < ntile; ti++) {
        const int t = bid + ti * grid;
        const int m_tile = t & 63;
        const int n_tile = t >> 6;

        float acc[4][8][4];
        #pragma unroll
        for (int mt = 0; mt < 4; mt++)
            #pragma unroll
            for (int nt = 0; nt < 8; nt++)
                #pragma unroll
                for (int q = 0; q < 4; q++) acc[mt][nt][q] = 0.0f;

        // 32 pairs of chunks; both waits up front, barrier-free pair body,
        // one __syncthreads per pair
        for (int cp = 0; cp < KCHUNKS / 2; cp++, j += 2) {
            const int s0 = (int)(j & (STAGES - 1));          // 0 or 2
            const int s1 = s0 + 1;
            const int ph = (int)((j >> 2) & 1);              // shared parity
            MBARRIER_WAIT_PARITY(mb_full + 8 * s0, ph);
            MBARRIER_WAIT_PARITY(mb_full + 8 * s1, ph);

            #pragma unroll
            for (int half = 0; half < 2; half++) {
                const uint32_t Asm = data + (uint32_t)(s0 + half) * STAGE_BYTES;
                const uint32_t Bsm = Asm + A_BYTES;

                #pragma unroll
                for (int ks = 0; ks < 4; ks++) {
                    uint32_t a[4][4];
                    #pragma unroll
                    for (int mt = 0; mt < 4; mt++) {
                        uint32_t off = sw128((rowA + mt * 16u) * 128u + kbA + ks * 32u);
                        LDSM_X4(a[mt][0], a[mt][1], a[mt][2], a[mt][3], Asm + off);
                    }
                    uint32_t b[4][4];
                    #pragma unroll
                    for (int np = 0; np < 4; np++) {
                        uint32_t off = sw128((rowB + np * 16u) * 128u + kbB + ks * 32u);
                        LDSM_X4(b[np][0], b[np][1], b[np][2], b[np][3], Bsm + off);
                    }
                    #pragma unroll
                    for (int mt = 0; mt < 4; mt++)
                        #pragma unroll
                        for (int np = 0; np < 4; np++) {
                            MMA16816(acc[mt][2 * np],
                                     a[mt][0], a[mt][1], a[mt][2], a[mt][3],
                                     b[np][0], b[np][1]);
                            MMA16816(acc[mt][2 * np + 1],
                                     a[mt][0], a[mt][1], a[mt][2], a[mt][3],
                                     b[np][2], b[np][3]);
                        }
                }
            }

            __syncthreads();   // stages s0, s1 fully consumed by all warps
            // refill the JUST-FREED stages with chunks j+4 and j+5
            // ((j+4)&3 == s0, (j+5)&3 == s1); split across two threads
            if (tid == 0 && j + 4 < totchunks)
                issue_chunk(j + 4, bid, grid, data, mb_full);
            if (tid == 32 && j + 5 < totchunks)
                issue_chunk(j + 5, bid, grid, data, mb_full);
        }

        // epilogue (overlaps in-flight loads of the next tile's chunks)
        const int row0 = m_tile * 128 + wm * 64 + (lane >> 2);
        const int col0 = n_tile * 256 + wn * 64 + (lane & 3) * 2;
        #pragma unroll
        for (int nt = 0; nt < 8; nt++) {
            const int cc = col0 + nt * 8;
            const float2 bv = *(const float2*)(bias + cc);
            #pragma unroll
            for (int mt = 0; mt < 4; mt++) {
                const int r = row0 + mt * 16;
                STG64_CS(out + (size_t)r * OUTF + cc,
                         acc[mt][nt][0] + bv.x, acc[mt][nt][1] + bv.y);
                STG64_CS(out + (size_t)(r + 8) * OUTF + cc,
                         acc[mt][nt][2] + bv.x, acc[mt][nt][3] + bv.y);
            }
        }
    }
}

// ---------------- launch ------------------------------------------------------
extern "C" void kernel_launch(void* const* d_in, const int* in_sizes, int n_in,
                              void* d_out, int out_size) {
    const float* x    = (const float*)d_in[0];
    const float* w    = (const float*)d_in[1];
    const float* bias = (const float*)d_in[2];
    float* out = (float*)d_out;

    k_prep<<<1024, 256>>>((const float4*)w, x);   // absum partials + x->fp16
    k_thr<<<1, 256>>>();                          // threshold scalar
    k_quant_w<<<OUTF * INF / 8 / 256, 256>>>(w);  // ternarize + pack w

    int dev = 0, sms = 148;
    cudaGetDevice(&dev);
    cudaDeviceGetAttribute(&sms, cudaDevAttrMultiProcessorCount, dev);

    cudaFuncSetAttribute(k_gemm, cudaFuncAttributeMaxDynamicSharedMemorySize,
                         SMEM_BYTES);
    k_gemm<<<sms, 256, SMEM_BYTES>>>(out, bias, sms);
}

// round 15
// speedup vs baseline: 1.0192x; 1.0192x over previous
#include <cuda_runtime.h>
#include <cuda_fp16.h>
#include <cstdint>

// ---------------------------------------------------------------------------
// BitLinear: out = x @ absmean_quant(w)^T + bias
//   x: [8192, 4096] f32, w: [16384, 4096] f32, bias: [16384] f32
//   out: [8192, 16384] f32   (1.10 TFLOP GEMM)
//
// sm_103 (plain) -> legacy HMMA path (tcgen05 rejected by ptxas):
//   mma.sync.m16n8k16.f32.f16.f16.f32 + ldmatrix, cp.async.bulk + mbarrier.
// R15 = R12 (proven optimum: per-chunk waits interleaved with compute,
// pair-granular __syncthreads, 4-stage continuous ring, fused prep) with
// the post-sync refill split across tid0/tid32 (parallel TMA issue).
// ---------------------------------------------------------------------------

#define TOK   8192
#define INF   4096
#define OUTF  16384

// ---------------- device scratch (no cudaMalloc allowed) -------------------
__device__ double g_part[1024];  // absum partials (one slot per block, no init)
__device__ float  g_thr;         // 0.7 * mean|w|
// w packed: [n_tile256][k_chunk64][256x64 fp16 SW128-swizzled = 32KB]
__device__ __align__(1024) unsigned char g_wq[(size_t)OUTF * INF * 2];
// x packed: [m_tile128][k_chunk64][128x64 fp16 SW128-swizzled = 16KB]
__device__ __align__(1024) unsigned char g_xh[(size_t)TOK * INF * 2];

// ---------------- PTX helpers ----------------------------------------------
__device__ __forceinline__ uint32_t smem_u32(const void* p) {
    uint32_t a;
    asm("{ .reg .u64 t; cvta.to.shared.u64 t, %1; cvt.u32.u64 %0, t; }"
        : "=r"(a) : "l"(p));
    return a;
}

#define MBARRIER_INIT(addr, cnt) \
    asm volatile("mbarrier.init.shared.b64 [%0], %1;" :: "r"(addr), "r"(cnt) : "memory")

#define MBARRIER_EXPECT_TX(addr, bytes) \
    asm volatile("mbarrier.arrive.expect_tx.shared.b64 _, [%0], %1;" \
                 :: "r"(addr), "r"(bytes) : "memory")

#define MBARRIER_WAIT_PARITY(mbar_smem_addr, phase_parity) do { \
    uint32_t _mbar = (uint32_t)(mbar_smem_addr); \
    uint32_t _parity = (uint32_t)(phase_parity); \
    uint32_t _done; \
    asm volatile( \
        "{\n\t.reg .pred p;\n\t" \
        "mbarrier.try_wait.parity.acquire.cta.shared::cta.b64 p, [%1], %2;\n\t" \
        "selp.b32 %0, 1, 0, p;\n\t}" \
        : "=r"(_done) : "r"(_mbar), "r"(_parity) : "memory"); \
    if (!_done) { \
        asm volatile( \
            "{\n\t.reg .pred P1;\n\t" \
            "WAIT_LOOP_%=:\n\t" \
            "mbarrier.try_wait.parity.acquire.cta.shared::cta.b64 P1, [%0], %1, 0x989680;\n\t" \
            "@P1 bra.uni WAIT_DONE_%=;\n\t" \
            "bra.uni WAIT_LOOP_%=;\n\t" \
            "WAIT_DONE_%=:\n\t}" \
            :: "r"(_mbar), "r"(_parity) : "memory"); \
    } \
} while(0)

// 1D bulk copy gmem -> smem with mbarrier complete_tx (sm_90 baseline)
__device__ __forceinline__ void bulk_g2s(uint32_t dst, const void* src,
                                         uint32_t bytes, uint32_t mbar) {
    asm volatile(
        "cp.async.bulk.shared::cluster.global.mbarrier::complete_tx::bytes "
        "[%0], [%1], %2, [%3];"
        :: "r"(dst), "l"(src), "r"(bytes), "r"(mbar) : "memory");
}

#define LDSM_X4(r0, r1, r2, r3, addr) \
    asm volatile("ldmatrix.sync.aligned.m8n8.x4.shared.b16 {%0,%1,%2,%3}, [%4];" \
                 : "=r"(r0), "=r"(r1), "=r"(r2), "=r"(r3) : "r"(addr))

#define MMA16816(d, a0, a1, a2, a3, b0, b1) \
    asm volatile("mma.sync.aligned.m16n8k16.row.col.f32.f16.f16.f32 " \
                 "{%0,%1,%2,%3}, {%4,%5,%6,%7}, {%8,%9}, {%0,%1,%2,%3};" \
                 : "+f"((d)[0]), "+f"((d)[1]), "+f"((d)[2]), "+f"((d)[3]) \
                 : "r"(a0), "r"(a1), "r"(a2), "r"(a3), "r"(b0), "r"(b1))

// streaming (evict-first) store: keep L2 for A/B tiles
#define STG64_CS(ptr, vx, vy) \
    asm volatile("st.global.cs.v2.f32 [%0], {%1, %2};" \
                 :: "l"(ptr), "f"(vx), "f"(vy) : "memory")

__device__ __forceinline__ uint32_t sw128(uint32_t off) {
    return off ^ ((off >> 3) & 0x70);
}

// ---------------- prep kernels ----------------------------------------------
// fused: absum partials over w (1024 blocks, one slot each, no init needed)
// + x -> fp16 tiled+swizzled conversion (grid-stride).
__global__ void k_prep(const float4* __restrict__ w,
                       const float* __restrict__ x) {
    // ---- part 1: absum partial over w ----
    double s = 0.0;
    const int n4 = OUTF * INF / 4;
    for (int i = blockIdx.x * blockDim.x + threadIdx.x; i < n4;
         i += gridDim.x * blockDim.x) {
        float4 v = w[i];
        s += (double)fabsf(v.x) + (double)fabsf(v.y) +
             (double)fabsf(v.z) + (double)fabsf(v.w);
    }
    for (int o = 16; o; o >>= 1) s += __shfl_xor_sync(0xffffffffu, s, o);
    __shared__ double ws[8];
    if ((threadIdx.x & 31) == 0) ws[threadIdx.x >> 5] = s;
    __syncthreads();
    if (threadIdx.x == 0) {
        double t = 0.0;
        #pragma unroll
        for (int i = 0; i < 8; i++) t += ws[i];
        g_part[blockIdx.x] = t;
    }

    // ---- part 2: convert x -> fp16, tiled+swizzled (8 elems / item) ----
    const unsigned nitems = TOK * INF / 8;   // 4194304
    for (unsigned idx = blockIdx.x * blockDim.x + threadIdx.x; idx < nitems;
         idx += gridDim.x * blockDim.x) {
        unsigned m  = idx >> 9;
        unsigned k0 = (idx & 511u) << 3;
        const float4* p = (const float4*)(x + (size_t)m * INF + k0);
        float4 v0 = p[0], v1 = p[1];
        float a[8] = {v0.x, v0.y, v0.z, v0.w, v1.x, v1.y, v1.z, v1.w};
        unsigned hs[8];
        #pragma unroll
        for (int i = 0; i < 8; i++)
            hs[i] = (unsigned)__half_as_ushort(__float2half_rn(a[i]));
        uint4 u;
        u.x = hs[0] | (hs[1] << 16);
        u.y = hs[2] | (hs[3] << 16);
        u.z = hs[4] | (hs[5] << 16);
        u.w = hs[6] | (hs[7] << 16);
        uint32_t off = sw128((m & 127u) * 128u + (k0 & 63u) * 2u);
        size_t base = ((size_t)(m >> 7) * 64u + (k0 >> 6)) * 16384u + off;
        *(uint4*)(g_xh + base) = u;
    }
}

// reduce the 1024 partials to the threshold scalar
__global__ void k_thr() {
    double s = 0.0;
    for (int i = threadIdx.x; i < 1024; i += 256) s += g_part[i];
    for (int o = 16; o; o >>= 1) s += __shfl_xor_sync(0xffffffffu, s, o);
    __shared__ double ws[8];
    if ((threadIdx.x & 31) == 0) ws[threadIdx.x >> 5] = s;
    __syncthreads();
    if (threadIdx.x == 0) {
        double t = 0.0;
        #pragma unroll
        for (int i = 0; i < 8; i++) t += ws[i];
        g_thr = (float)(t * (0.7 / ((double)OUTF * (double)INF)));
    }
}

// ternarize w -> fp16, tiled+swizzled (8 elems / thread)
__global__ void k_quant_w(const float* __restrict__ w) {
    const float thr = g_thr;
    unsigned idx = blockIdx.x * 256u + threadIdx.x;   // 0 .. 8388607
    unsigned n  = idx >> 9;          // out-feature row
    unsigned k0 = (idx & 511u) << 3; // k group start
    const float4* p = (const float4*)(w + (size_t)n * INF + k0);
    float4 v0 = p[0], v1 = p[1];
    float a[8] = {v0.x, v0.y, v0.z, v0.w, v1.x, v1.y, v1.z, v1.w};
    unsigned hs[8];
    #pragma unroll
    for (int i = 0; i < 8; i++) {
        float t = a[i];
        hs[i] = (fabsf(t) >= thr) ? (t > 0.0f ? 0x3C00u : 0xBC00u) : 0u;
    }
    uint4 u;
    u.x = hs[0] | (hs[1] << 16);
    u.y = hs[2] | (hs[3] << 16);
    u.z = hs[4] | (hs[5] << 16);
    u.w = hs[6] | (hs[7] << 16);
    uint32_t off = sw128((n & 255u) * 128u + (k0 & 63u) * 2u);
    size_t base = ((size_t)(n >> 8) * 64u + (k0 >> 6)) * 32768u + off;
    *(uint4*)(g_wq + base) = u;
}

// ---------------- GEMM (R12 schedule) ----------------------------------------
// Persistent CTAs, 1/SM, 8 warps (2M x 4N, warp tile 64x64). CTA tile
// 128x256xK64. 4-stage continuous cp.async.bulk ring, per-chunk waits
// interleaved with compute, __syncthreads once per pair; refill split
// across tid0/tid32.
static constexpr int TILES = 4096;                   // 64 m x 64 n
static constexpr int KCHUNKS = INF / 64;             // 64 (even)
static constexpr int STAGES = 4;
static constexpr uint32_t A_BYTES = 128u * 128u;     // 16KB
static constexpr uint32_t B_BYTES = 256u * 128u;     // 32KB
static constexpr uint32_t STAGE_BYTES = A_BYTES + B_BYTES;  // 48KB
static constexpr uint32_t SMEM_BYTES = 1024u + STAGES * STAGE_BYTES;

__device__ __forceinline__ void issue_chunk(long j, int bid, int grid,
                                            uint32_t data, uint32_t mb_full) {
    const int t = bid + (int)(j >> 6) * grid;   // tile for this chunk
    const int c = (int)(j & 63);
    const int m = t & 63;
    const int n = t >> 6;
    const int s = (int)(j & (STAGES - 1));
    const uint32_t st = data + (uint32_t)s * STAGE_BYTES;
    MBARRIER_EXPECT_TX(mb_full + 8 * s, STAGE_BYTES);
    bulk_g2s(st, g_xh + ((size_t)m * 64u + c) * A_BYTES, A_BYTES, mb_full + 8 * s);
    bulk_g2s(st + A_BYTES, g_wq + ((size_t)n * 64u + c) * B_BYTES, B_BYTES,
             mb_full + 8 * s);
}

__global__ void __launch_bounds__(256, 1) k_gemm(float* __restrict__ out,
                                                 const float* __restrict__ bias,
                                                 int grid) {
    extern __shared__ char smem_raw[];
    uint32_t base = (smem_u32(smem_raw) + 1023u) & ~1023u;
    const uint32_t mb_full = base;           // STAGES x 8B mbarriers
    const uint32_t data    = base + 1024u;

    const int tid  = threadIdx.x;
    const int wid  = tid >> 5;
    const int lane = tid & 31;
    const int wm = wid & 1;        // 2 warps along M
    const int wn = wid >> 1;       // 4 warps along N
    const int bid = blockIdx.x;

    if (tid == 0) {
        #pragma unroll
        for (int s = 0; s < STAGES; s++) MBARRIER_INIT(mb_full + 8 * s, 1);
    }
    __syncthreads();

    const int ntile = (bid < TILES) ? ((TILES - 1 - bid) / grid + 1) : 0;
    if (ntile == 0) return;
    const long totchunks = (long)ntile * KCHUNKS;

    // prologue: fill all STAGES slots of the continuous stream
    if (tid == 0) {
        const long pre = totchunks < STAGES ? totchunks : STAGES;
        for (long j = 0; j < pre; j++) issue_chunk(j, bid, grid, data, mb_full);
    }

    // per-thread ldmatrix sub-offsets (un-swizzled), swizzle applied per access
    const uint32_t rowA = (uint32_t)(wm * 64 + (lane & 7) + ((lane >> 3) & 1) * 8);
    const uint32_t kbA  = (uint32_t)((lane >> 4) * 16);
    const uint32_t rowB = (uint32_t)(wn * 64 + ((lane >> 4) & 1) * 8 + (lane & 7));
    const uint32_t kbB  = (uint32_t)(((lane >> 3) & 1) * 16);

    int ph = 0;
    long j = 0;
    for (int ti = 0; ti < ntile; ti++) {
        const int t = bid + ti * grid;
        const int m_tile = t & 63;
        const int n_tile = t >> 6;

        float acc[4][8][4];
        #pragma unroll
        for (int mt = 0; mt < 4; mt++)
            #pragma unroll
            for (int nt = 0; nt < 8; nt++)
                #pragma unroll
                for (int q = 0; q < 4; q++) acc[mt][nt][q] = 0.0f;

        // 32 pairs of chunks; __syncthreads once per pair
        for (int cp = 0; cp < KCHUNKS / 2; cp++) {
            #pragma unroll
            for (int half = 0; half < 2; half++, j++) {
                const int s = (int)(j & (STAGES - 1));
                MBARRIER_WAIT_PARITY(mb_full + 8 * s, ph);
                const uint32_t Asm = data + (uint32_t)s * STAGE_BYTES;
                const uint32_t Bsm = Asm + A_BYTES;

                #pragma unroll
                for (int ks = 0; ks < 4; ks++) {
                    uint32_t a[4][4];
                    #pragma unroll
                    for (int mt = 0; mt < 4; mt++) {
                        uint32_t off = sw128((rowA + mt * 16u) * 128u + kbA + ks * 32u);
                        LDSM_X4(a[mt][0], a[mt][1], a[mt][2], a[mt][3], Asm + off);
                    }
                    uint32_t b[4][4];
                    #pragma unroll
                    for (int np = 0; np < 4; np++) {
                        uint32_t off = sw128((rowB + np * 16u) * 128u + kbB + ks * 32u);
                        LDSM_X4(b[np][0], b[np][1], b[np][2], b[np][3], Bsm + off);
                    }
                    #pragma unroll
                    for (int mt = 0; mt < 4; mt++)
                        #pragma unroll
                        for (int np = 0; np < 4; np++) {
                            MMA16816(acc[mt][2 * np],
                                     a[mt][0], a[mt][1], a[mt][2], a[mt][3],
                                     b[np][0], b[np][1]);
                            MMA16816(acc[mt][2 * np + 1],
                                     a[mt][0], a[mt][1], a[mt][2], a[mt][3],
                                     b[np][2], b[np][3]);
                        }
                }
                if (s == STAGES - 1) ph ^= 1;
            }

            __syncthreads();   // stages (j-2)&3 and (j-1)&3 fully consumed
            // refill the just-freed stages; split across two warps
            if (tid == 0 && j + 2 < totchunks)
                issue_chunk(j + 2, bid, grid, data, mb_full);
            if (tid == 32 && j + 3 < totchunks)
                issue_chunk(j + 3, bid, grid, data, mb_full);
        }

        // epilogue (overlaps in-flight loads of the next tile's chunks)
        const int row0 = m_tile * 128 + wm * 64 + (lane >> 2);
        const int col0 = n_tile * 256 + wn * 64 + (lane & 3) * 2;
        #pragma unroll
        for (int nt = 0; nt < 8; nt++) {
            const int cc = col0 + nt * 8;
            const float2 bv = *(const float2*)(bias + cc);
            #pragma unroll
            for (int mt = 0; mt < 4; mt++) {
                const int r = row0 + mt * 16;
                STG64_CS(out + (size_t)r * OUTF + cc,
                         acc[mt][nt][0] + bv.x, acc[mt][nt][1] + bv.y);
                STG64_CS(out + (size_t)(r + 8) * OUTF + cc,
                         acc[mt][nt][2] + bv.x, acc[mt][nt][3] + bv.y);
            }
        }
    }
}

// ---------------- launch ------------------------------------------------------
extern "C" void kernel_launch(void* const* d_in, const int* in_sizes, int n_in,
                              void* d_out, int out_size) {
    const float* x    = (const float*)d_in[0];
    const float* w    = (const float*)d_in[1];
    const float* bias = (const float*)d_in[2];
    float* out = (float*)d_out;

    k_prep<<<1024, 256>>>((const float4*)w, x);   // absum partials + x->fp16
    k_thr<<<1, 256>>>();                          // threshold scalar
    k_quant_w<<<OUTF * INF / 8 / 256, 256>>>(w);  // ternarize + pack w

    int dev = 0, sms = 148;
    cudaGetDevice(&dev);
    cudaDeviceGetAttribute(&sms, cudaDevAttrMultiProcessorCount, dev);

    cudaFuncSetAttribute(k_gemm, cudaFuncAttributeMaxDynamicSharedMemorySize,
                         SMEM_BYTES);
    k_gemm<<<sms, 256, SMEM_BYTES>>>(out, bias, sms);
}

// round 16
// speedup vs baseline: 1.0367x; 1.0171x over previous
#include <cuda_runtime.h>
#include <cuda_fp16.h>
#include <cstdint>

// ---------------------------------------------------------------------------
// BitLinear: out = x @ absmean_quant(w)^T + bias
//   x: [8192, 4096] f32, w: [16384, 4096] f32, bias: [16384] f32
//   out: [8192, 16384] f32   (1.10 TFLOP GEMM)
//
// sm_103 (plain) -> legacy HMMA path (tcgen05 rejected by ptxas):
//   mma.sync.m16n8k16.f32.f16.f16.f32 + ldmatrix, cp.async.bulk + mbarrier.
// FINAL (R12 verbatim — measured optimum across 14 variants):
//  - ternary w exact in fp16, x->fp16 (rel_err 2.1e-4, 5x under threshold)
//  - prep: fused absum+x-convert, threshold reduce, w ternarize+pack, all
//    writing pre-tiled pre-SW128-swizzled fp16 blocks
//  - GEMM: persistent CTAs (1/SM), 8 warps (2Mx4N, warp tile 64x64), CTA
//    tile 128x256xK64, 4-stage continuous cp.async.bulk ring across tiles,
//    per-chunk mbarrier waits interleaved with compute, __syncthreads once
//    per chunk-PAIR, tid0 refills both freed stages, streaming stores.
//  - measured: tensor pipe 88% of elapsed (HMMA issue floor).
// ---------------------------------------------------------------------------

#define TOK   8192
#define INF   4096
#define OUTF  16384

// ---------------- device scratch (no cudaMalloc allowed) -------------------
__device__ double g_part[1024];  // absum partials (one slot per block, no init)
__device__ float  g_thr;         // 0.7 * mean|w|
// w packed: [n_tile256][k_chunk64][256x64 fp16 SW128-swizzled = 32KB]
__device__ __align__(1024) unsigned char g_wq[(size_t)OUTF * INF * 2];
// x packed: [m_tile128][k_chunk64][128x64 fp16 SW128-swizzled = 16KB]
__device__ __align__(1024) unsigned char g_xh[(size_t)TOK * INF * 2];

// ---------------- PTX helpers ----------------------------------------------
__device__ __forceinline__ uint32_t smem_u32(const void* p) {
    uint32_t a;
    asm("{ .reg .u64 t; cvta.to.shared.u64 t, %1; cvt.u32.u64 %0, t; }"
        : "=r"(a) : "l"(p));
    return a;
}

#define MBARRIER_INIT(addr, cnt) \
    asm volatile("mbarrier.init.shared.b64 [%0], %1;" :: "r"(addr), "r"(cnt) : "memory")

#define MBARRIER_EXPECT_TX(addr, bytes) \
    asm volatile("mbarrier.arrive.expect_tx.shared.b64 _, [%0], %1;" \
                 :: "r"(addr), "r"(bytes) : "memory")

#define MBARRIER_WAIT_PARITY(mbar_smem_addr, phase_parity) do { \
    uint32_t _mbar = (uint32_t)(mbar_smem_addr); \
    uint32_t _parity = (uint32_t)(phase_parity); \
    uint32_t _done; \
    asm volatile( \
        "{\n\t.reg .pred p;\n\t" \
        "mbarrier.try_wait.parity.acquire.cta.shared::cta.b64 p, [%1], %2;\n\t" \
        "selp.b32 %0, 1, 0, p;\n\t}" \
        : "=r"(_done) : "r"(_mbar), "r"(_parity) : "memory"); \
    if (!_done) { \
        asm volatile( \
            "{\n\t.reg .pred P1;\n\t" \
            "WAIT_LOOP_%=:\n\t" \
            "mbarrier.try_wait.parity.acquire.cta.shared::cta.b64 P1, [%0], %1, 0x989680;\n\t" \
            "@P1 bra.uni WAIT_DONE_%=;\n\t" \
            "bra.uni WAIT_LOOP_%=;\n\t" \
            "WAIT_DONE_%=:\n\t}" \
            :: "r"(_mbar), "r"(_parity) : "memory"); \
    } \
} while(0)

// 1D bulk copy gmem -> smem with mbarrier complete_tx (sm_90 baseline)
__device__ __forceinline__ void bulk_g2s(uint32_t dst, const void* src,
                                         uint32_t bytes, uint32_t mbar) {
    asm volatile(
        "cp.async.bulk.shared::cluster.global.mbarrier::complete_tx::bytes "
        "[%0], [%1], %2, [%3];"
        :: "r"(dst), "l"(src), "r"(bytes), "r"(mbar) : "memory");
}

#define LDSM_X4(r0, r1, r2, r3, addr) \
    asm volatile("ldmatrix.sync.aligned.m8n8.x4.shared.b16 {%0,%1,%2,%3}, [%4];" \
                 : "=r"(r0), "=r"(r1), "=r"(r2), "=r"(r3) : "r"(addr))

#define MMA16816(d, a0, a1, a2, a3, b0, b1) \
    asm volatile("mma.sync.aligned.m16n8k16.row.col.f32.f16.f16.f32 " \
                 "{%0,%1,%2,%3}, {%4,%5,%6,%7}, {%8,%9}, {%0,%1,%2,%3};" \
                 : "+f"((d)[0]), "+f"((d)[1]), "+f"((d)[2]), "+f"((d)[3]) \
                 : "r"(a0), "r"(a1), "r"(a2), "r"(a3), "r"(b0), "r"(b1))

// streaming (evict-first) store: keep L2 for A/B tiles
#define STG64_CS(ptr, vx, vy) \
    asm volatile("st.global.cs.v2.f32 [%0], {%1, %2};" \
                 :: "l"(ptr), "f"(vx), "f"(vy) : "memory")

__device__ __forceinline__ uint32_t sw128(uint32_t off) {
    return off ^ ((off >> 3) & 0x70);
}

// ---------------- prep kernels ----------------------------------------------
// fused: absum partials over w (1024 blocks, one slot each, no init needed)
// + x -> fp16 tiled+swizzled conversion (grid-stride).
__global__ void k_prep(const float4* __restrict__ w,
                       const float* __restrict__ x) {
    // ---- part 1: absum partial over w ----
    double s = 0.0;
    const int n4 = OUTF * INF / 4;
    for (int i = blockIdx.x * blockDim.x + threadIdx.x; i < n4;
         i += gridDim.x * blockDim.x) {
        float4 v = w[i];
        s += (double)fabsf(v.x) + (double)fabsf(v.y) +
             (double)fabsf(v.z) + (double)fabsf(v.w);
    }
    for (int o = 16; o; o >>= 1) s += __shfl_xor_sync(0xffffffffu, s, o);
    __shared__ double ws[8];
    if ((threadIdx.x & 31) == 0) ws[threadIdx.x >> 5] = s;
    __syncthreads();
    if (threadIdx.x == 0) {
        double t = 0.0;
        #pragma unroll
        for (int i = 0; i < 8; i++) t += ws[i];
        g_part[blockIdx.x] = t;
    }

    // ---- part 2: convert x -> fp16, tiled+swizzled (8 elems / item) ----
    const unsigned nitems = TOK * INF / 8;   // 4194304
    for (unsigned idx = blockIdx.x * blockDim.x + threadIdx.x; idx < nitems;
         idx += gridDim.x * blockDim.x) {
        unsigned m  = idx >> 9;
        unsigned k0 = (idx & 511u) << 3;
        const float4* p = (const float4*)(x + (size_t)m * INF + k0);
        float4 v0 = p[0], v1 = p[1];
        float a[8] = {v0.x, v0.y, v0.z, v0.w, v1.x, v1.y, v1.z, v1.w};
        unsigned hs[8];
        #pragma unroll
        for (int i = 0; i < 8; i++)
            hs[i] = (unsigned)__half_as_ushort(__float2half_rn(a[i]));
        uint4 u;
        u.x = hs[0] | (hs[1] << 16);
        u.y = hs[2] | (hs[3] << 16);
        u.z = hs[4] | (hs[5] << 16);
        u.w = hs[6] | (hs[7] << 16);
        uint32_t off = sw128((m & 127u) * 128u + (k0 & 63u) * 2u);
        size_t base = ((size_t)(m >> 7) * 64u + (k0 >> 6)) * 16384u + off;
        *(uint4*)(g_xh + base) = u;
    }
}

// reduce the 1024 partials to the threshold scalar
__global__ void k_thr() {
    double s = 0.0;
    for (int i = threadIdx.x; i < 1024; i += 256) s += g_part[i];
    for (int o = 16; o; o >>= 1) s += __shfl_xor_sync(0xffffffffu, s, o);
    __shared__ double ws[8];
    if ((threadIdx.x & 31) == 0) ws[threadIdx.x >> 5] = s;
    __syncthreads();
    if (threadIdx.x == 0) {
        double t = 0.0;
        #pragma unroll
        for (int i = 0; i < 8; i++) t += ws[i];
        g_thr = (float)(t * (0.7 / ((double)OUTF * (double)INF)));
    }
}

// ternarize w -> fp16, tiled+swizzled (8 elems / thread)
__global__ void k_quant_w(const float* __restrict__ w) {
    const float thr = g_thr;
    unsigned idx = blockIdx.x * 256u + threadIdx.x;   // 0 .. 8388607
    unsigned n  = idx >> 9;          // out-feature row
    unsigned k0 = (idx & 511u) << 3; // k group start
    const float4* p = (const float4*)(w + (size_t)n * INF + k0);
    float4 v0 = p[0], v1 = p[1];
    float a[8] = {v0.x, v0.y, v0.z, v0.w, v1.x, v1.y, v1.z, v1.w};
    unsigned hs[8];
    #pragma unroll
    for (int i = 0; i < 8; i++) {
        float t = a[i];
        hs[i] = (fabsf(t) >= thr) ? (t > 0.0f ? 0x3C00u : 0xBC00u) : 0u;
    }
    uint4 u;
    u.x = hs[0] | (hs[1] << 16);
    u.y = hs[2] | (hs[3] << 16);
    u.z = hs[4] | (hs[5] << 16);
    u.w = hs[6] | (hs[7] << 16);
    uint32_t off = sw128((n & 255u) * 128u + (k0 & 63u) * 2u);
    size_t base = ((size_t)(n >> 8) * 64u + (k0 >> 6)) * 32768u + off;
    *(uint4*)(g_wq + base) = u;
}

// ---------------- GEMM (R12, proven) -----------------------------------------
// Persistent CTAs, 1/SM, 8 warps (2M x 4N, warp tile 64x64). CTA tile
// 128x256xK64. 4-stage continuous cp.async.bulk ring, __syncthreads every
// TWO chunks (pair-synced), TMA for 2 chunks issued right after each sync.
static constexpr int TILES = 4096;                   // 64 m x 64 n
static constexpr int KCHUNKS = INF / 64;             // 64 (even)
static constexpr int STAGES = 4;
static constexpr uint32_t A_BYTES = 128u * 128u;     // 16KB
static constexpr uint32_t B_BYTES = 256u * 128u;     // 32KB
static constexpr uint32_t STAGE_BYTES = A_BYTES + B_BYTES;  // 48KB
static constexpr uint32_t SMEM_BYTES = 1024u + STAGES * STAGE_BYTES;

__device__ __forceinline__ void issue_chunk(long j, int bid, int grid,
                                            uint32_t data, uint32_t mb_full) {
    const int t = bid + (int)(j >> 6) * grid;   // tile for this chunk
    const int c = (int)(j & 63);
    const int m = t & 63;
    const int n = t >> 6;
    const int s = (int)(j & (STAGES - 1));
    const uint32_t st = data + (uint32_t)s * STAGE_BYTES;
    MBARRIER_EXPECT_TX(mb_full + 8 * s, STAGE_BYTES);
    bulk_g2s(st, g_xh + ((size_t)m * 64u + c) * A_BYTES, A_BYTES, mb_full + 8 * s);
    bulk_g2s(st + A_BYTES, g_wq + ((size_t)n * 64u + c) * B_BYTES, B_BYTES,
             mb_full + 8 * s);
}

__global__ void __launch_bounds__(256, 1) k_gemm(float* __restrict__ out,
                                                 const float* __restrict__ bias,
                                                 int grid) {
    extern __shared__ char smem_raw[];
    uint32_t base = (smem_u32(smem_raw) + 1023u) & ~1023u;
    const uint32_t mb_full = base;           // STAGES x 8B mbarriers
    const uint32_t data    = base + 1024u;

    const int tid  = threadIdx.x;
    const int wid  = tid >> 5;
    const int lane = tid & 31;
    const int wm = wid & 1;        // 2 warps along M
    const int wn = wid >> 1;       // 4 warps along N
    const int bid = blockIdx.x;

    if (tid == 0) {
        #pragma unroll
        for (int s = 0; s < STAGES; s++) MBARRIER_INIT(mb_full + 8 * s, 1);
    }
    __syncthreads();

    const int ntile = (bid < TILES) ? ((TILES - 1 - bid) / grid + 1) : 0;
    if (ntile == 0) return;
    const long totchunks = (long)ntile * KCHUNKS;

    // prologue: fill all STAGES slots of the continuous stream
    if (tid == 0) {
        const long pre = totchunks < STAGES ? totchunks : STAGES;
        for (long j = 0; j < pre; j++) issue_chunk(j, bid, grid, data, mb_full);
    }

    // per-thread ldmatrix sub-offsets (un-swizzled), swizzle applied per access
    const uint32_t rowA = (uint32_t)(wm * 64 + (lane & 7) + ((lane >> 3) & 1) * 8);
    const uint32_t kbA  = (uint32_t)((lane >> 4) * 16);
    const uint32_t rowB = (uint32_t)(wn * 64 + ((lane >> 4) & 1) * 8 + (lane & 7));
    const uint32_t kbB  = (uint32_t)(((lane >> 3) & 1) * 16);

    int ph = 0;
    long j = 0;
    for (int ti = 0; ti < ntile; ti++) {
        const int t = bid + ti * grid;
        const int m_tile = t & 63;
        const int n_tile = t >> 6;

        float acc[4][8][4];
        #pragma unroll
        for (int mt = 0; mt < 4; mt++)
            #pragma unroll
            for (int nt = 0; nt < 8; nt++)
                #pragma unroll
                for (int q = 0; q < 4; q++) acc[mt][nt][q] = 0.0f;

        // 32 pairs of chunks; __syncthreads once per pair
        for (int cp = 0; cp < KCHUNKS / 2; cp++) {
            #pragma unroll
            for (int half = 0; half < 2; half++, j++) {
                const int s = (int)(j & (STAGES - 1));
                MBARRIER_WAIT_PARITY(mb_full + 8 * s, ph);
                const uint32_t Asm = data + (uint32_t)s * STAGE_BYTES;
                const uint32_t Bsm = Asm + A_BYTES;

                #pragma unroll
                for (int ks = 0; ks < 4; ks++) {
                    uint32_t a[4][4];
                    #pragma unroll
                    for (int mt = 0; mt < 4; mt++) {
                        uint32_t off = sw128((rowA + mt * 16u) * 128u + kbA + ks * 32u);
                        LDSM_X4(a[mt][0], a[mt][1], a[mt][2], a[mt][3], Asm + off);
                    }
                    uint32_t b[4][4];
                    #pragma unroll
                    for (int np = 0; np < 4; np++) {
                        uint32_t off = sw128((rowB + np * 16u) * 128u + kbB + ks * 32u);
                        LDSM_X4(b[np][0], b[np][1], b[np][2], b[np][3], Bsm + off);
                    }
                    #pragma unroll
                    for (int mt = 0; mt < 4; mt++)
                        #pragma unroll
                        for (int np = 0; np < 4; np++) {
                            MMA16816(acc[mt][2 * np],
                                     a[mt][0], a[mt][1], a[mt][2], a[mt][3],
                                     b[np][0], b[np][1]);
                            MMA16816(acc[mt][2 * np + 1],
                                     a[mt][0], a[mt][1], a[mt][2], a[mt][3],
                                     b[np][2], b[np][3]);
                        }
                }
                if (s == STAGES - 1) ph ^= 1;
            }

            __syncthreads();   // stages (j-2)&3 and (j-1)&3 fully consumed
            if (tid == 0) {
                if (j + 2 < totchunks) issue_chunk(j + 2, bid, grid, data, mb_full);
                if (j + 3 < totchunks) issue_chunk(j + 3, bid, grid, data, mb_full);
            }
        }

        // epilogue (overlaps in-flight loads of the next tile's chunks)
        const int row0 = m_tile * 128 + wm * 64 + (lane >> 2);
        const int col0 = n_tile * 256 + wn * 64 + (lane & 3) * 2;
        #pragma unroll
        for (int nt = 0; nt < 8; nt++) {
            const int cc = col0 + nt * 8;
            const float2 bv = *(const float2*)(bias + cc);
            #pragma unroll
            for (int mt = 0; mt < 4; mt++) {
                const int r = row0 + mt * 16;
                STG64_CS(out + (size_t)r * OUTF + cc,
                         acc[mt][nt][0] + bv.x, acc[mt][nt][1] + bv.y);
                STG64_CS(out + (size_t)(r + 8) * OUTF + cc,
                         acc[mt][nt][2] + bv.x, acc[mt][nt][3] + bv.y);
            }
        }
    }
}

// ---------------- launch ------------------------------------------------------
extern "C" void kernel_launch(void* const* d_in, const int* in_sizes, int n_in,
                              void* d_out, int out_size) {
    const float* x    = (const float*)d_in[0];
    const float* w    = (const float*)d_in[1];
    const float* bias = (const float*)d_in[2];
    float* out = (float*)d_out;

    k_prep<<<1024, 256>>>((const float4*)w, x);   // absum partials + x->fp16
    k_thr<<<1, 256>>>();                          // threshold scalar
    k_quant_w<<<OUTF * INF / 8 / 256, 256>>>(w);  // ternarize + pack w

    int dev = 0, sms = 148;
    cudaGetDevice(&dev);
    cudaDeviceGetAttribute(&sms, cudaDevAttrMultiProcessorCount, dev);

    cudaFuncSetAttribute(k_gemm, cudaFuncAttributeMaxDynamicSharedMemorySize,
                         SMEM_BYTES);
    k_gemm<<<sms, 256, SMEM_BYTES>>>(out, bias, sms);
}